// round 10
// baseline (speedup 1.0000x reference)
#include <cuda_runtime.h>
#include <cuda_fp16.h>
#include <cstdint>

// ---------------------------------------------------------------------------
// Shifted-window MSA. B=8, NSEQ=16384, C=256, P=64, SHIFT=32, NH=8, HD=32.
//   K0: cvt x(rolled)->fp16, w_qkv->fp16, w_out->fp16
//   K1: QKV GEMM (fp16 mma, warp tile 64x64)   -> g_qkv (fp16)
//   K2: attention (fp16 mma, per window-head)  -> g_att (fp16)
//   K3: out GEMM (fp16 mma, roll on write)     -> d_out (fp32)
// tcgen05 unusable: harness ptxas targets sm_103 (no 'a' features).
// ---------------------------------------------------------------------------

#define BATCH   8
#define NSEQ    16384
#define CDIM    256
#define PWIN    64
#define SHIFT   32
#define NHEADS  8
#define HDIM    32
#define MTOT    (BATCH * NSEQ)
#define QKV_N   768
#define NWIN    (MTOT / PWIN)
#define WPB     (NSEQ / PWIN)

__device__ __half g_qkv [(size_t)MTOT * QKV_N];
__device__ __half g_att [(size_t)MTOT * CDIM];
__device__ __half g_xh  [(size_t)MTOT * CDIM];
__device__ __half g_wqkvh[(size_t)QKV_N * CDIM];
__device__ __half g_wouth[(size_t)CDIM * CDIM];

// ---------------------------------------------------------------------------
__device__ __forceinline__ uint32_t smem_u32(const void* p) {
    return (uint32_t)__cvta_generic_to_shared(p);
}
__device__ __forceinline__ void mma_f16(float (&d)[4],
                                        const uint32_t (&a)[4],
                                        const uint32_t (&b)[2]) {
    asm volatile(
        "mma.sync.aligned.m16n8k16.row.col.f32.f16.f16.f32 "
        "{%0,%1,%2,%3}, {%4,%5,%6,%7}, {%8,%9}, {%0,%1,%2,%3};"
        : "+f"(d[0]), "+f"(d[1]), "+f"(d[2]), "+f"(d[3])
        : "r"(a[0]), "r"(a[1]), "r"(a[2]), "r"(a[3]), "r"(b[0]), "r"(b[1]));
}
__device__ __forceinline__ void ldsm_x4(uint32_t (&r)[4], uint32_t addr) {
    asm volatile("ldmatrix.sync.aligned.m8n8.x4.shared.b16 {%0,%1,%2,%3}, [%4];"
        : "=r"(r[0]), "=r"(r[1]), "=r"(r[2]), "=r"(r[3]) : "r"(addr));
}
__device__ __forceinline__ uint32_t h2u(__half2 h) {
    return *reinterpret_cast<uint32_t*>(&h);
}

// ---------------------------------------------------------------------------
// FP16 GEMM: C[m,n] = sum_k A[m,k]*W[n,k] + bias[n]
// BM=BN=128, BK=32, 128 threads = 4 warps, warp tile 64x64 (2x2 warps).
// Per k-step per warp: 8 LDSM.x4 -> 32 MMA (128 smem B/MMA).
// Smem stride 40 halves (80B): LDSM row-phase banks = 5r mod 8 (permutation).
// ---------------------------------------------------------------------------
#define HBK 32
#define NKT (CDIM / HBK)   // 8

template<bool ROLL_OUT, typename OutT>
__global__ void __launch_bounds__(128, 2)
gemm_f16_kernel(const __half* __restrict__ A,
                const __half* __restrict__ W,
                const float* __restrict__ bias,
                OutT* __restrict__ Cout,
                int Ncols)
{
    __shared__ __half As[128][40];
    __shared__ __half Bs[128][40];

    const int bm = blockIdx.y * 128;
    const int bn = blockIdx.x * 128;

    const int t    = threadIdx.x;
    const int warp = t >> 5;
    const int lane = t & 31;
    const int g    = lane >> 2;
    const int tg   = lane & 3;

    const int wm = (warp & 1) * 64;
    const int wn = (warp >> 1) * 64;

    // gmem load map: 128 rows x 4 chunks(16B) per matrix, 4 chunks/thread each
    int arow[4], ac[4];
#pragma unroll
    for (int i = 0; i < 4; i++) {
        int id = t + i * 128;
        arow[i] = id >> 2;
        ac[i]   = id & 3;
    }
    const __half* Ab = A + (size_t)bm * CDIM;
    const __half* Wb = W + (size_t)bn * CDIM;

    // ldmatrix base addresses
    uint32_t aAddr[4], bAddr[4];
#pragma unroll
    for (int mt = 0; mt < 4; mt++)
        aAddr[mt] = smem_u32(&As[wm + mt * 16 + (lane & 15)][(lane >> 4) * 8]);
#pragma unroll
    for (int np = 0; np < 4; np++)
        bAddr[np] = smem_u32(&Bs[wn + np * 16 + ((lane >> 4) << 3) + (lane & 7)]
                                [((lane >> 3) & 1) * 8]);

    float acc[4][8][4];
#pragma unroll
    for (int mt = 0; mt < 4; mt++)
#pragma unroll
        for (int nt = 0; nt < 8; nt++)
#pragma unroll
            for (int r = 0; r < 4; r++) acc[mt][nt][r] = 0.0f;

    // prefetch kt=0
    uint4 av[4], bv[4];
#pragma unroll
    for (int i = 0; i < 4; i++) {
        av[i] = *(const uint4*)(Ab + (size_t)arow[i] * CDIM + ac[i] * 8);
        bv[i] = *(const uint4*)(Wb + (size_t)arow[i] * CDIM + ac[i] * 8);
    }

#pragma unroll 1
    for (int kt = 0; kt < NKT; kt++) {
        __syncthreads();   // previous iteration's fragment reads done
#pragma unroll
        for (int i = 0; i < 4; i++) {
            *(uint4*)&As[arow[i]][ac[i] * 8] = av[i];
            *(uint4*)&Bs[arow[i]][ac[i] * 8] = bv[i];
        }
        __syncthreads();

        // prefetch next tile (LDG latency overlaps the MMA block below)
        if (kt + 1 < NKT) {
            const int k0 = (kt + 1) * HBK;
#pragma unroll
            for (int i = 0; i < 4; i++) {
                av[i] = *(const uint4*)(Ab + (size_t)arow[i] * CDIM + k0 + ac[i] * 8);
                bv[i] = *(const uint4*)(Wb + (size_t)arow[i] * CDIM + k0 + ac[i] * 8);
            }
        }

#pragma unroll
        for (int ks = 0; ks < 2; ks++) {
            const uint32_t koff = ks * 32;   // 16 halves
            uint32_t afr[4][4], bp[4][4];
#pragma unroll
            for (int mt = 0; mt < 4; mt++) ldsm_x4(afr[mt], aAddr[mt] + koff);
#pragma unroll
            for (int np = 0; np < 4; np++) ldsm_x4(bp[np], bAddr[np] + koff);
#pragma unroll
            for (int mt = 0; mt < 4; mt++)
#pragma unroll
                for (int nt = 0; nt < 8; nt++) {
                    uint32_t bfr[2] = { bp[nt >> 1][(nt & 1) * 2],
                                        bp[nt >> 1][(nt & 1) * 2 + 1] };
                    mma_f16(acc[mt][nt], afr[mt], bfr);
                }
        }
    }

    // ---- epilogue: bias + optional output roll ----
#pragma unroll
    for (int mt = 0; mt < 4; mt++) {
        int m0 = bm + wm + mt * 16 + g;
        int m1 = m0 + 8;
        int bi0 = m0 >> 14, t0 = m0 & 16383;
        int bi1 = m1 >> 14, t1 = m1 & 16383;
        int d0 = ROLL_OUT ? ((t0 + SHIFT) & 16383) : t0;
        int d1 = ROLL_OUT ? ((t1 + SHIFT) & 16383) : t1;
        OutT* row0 = Cout + (size_t)((bi0 << 14) + d0) * Ncols;
        OutT* row1 = Cout + (size_t)((bi1 << 14) + d1) * Ncols;
#pragma unroll
        for (int nt = 0; nt < 8; nt++) {
            int col = bn + wn + nt * 8 + 2 * tg;
            float b0 = bias[col], b1 = bias[col + 1];
            if constexpr (sizeof(OutT) == 4) {
                *(float2*)((float*)row0 + col) =
                    make_float2(acc[mt][nt][0] + b0, acc[mt][nt][1] + b1);
                *(float2*)((float*)row1 + col) =
                    make_float2(acc[mt][nt][2] + b0, acc[mt][nt][3] + b1);
            } else {
                *(uint32_t*)((__half*)row0 + col) =
                    h2u(__floats2half2_rn(acc[mt][nt][0] + b0, acc[mt][nt][1] + b1));
                *(uint32_t*)((__half*)row1 + col) =
                    h2u(__floats2half2_rn(acc[mt][nt][2] + b0, acc[mt][nt][3] + b1));
            }
        }
    }
}

// ---------------------------------------------------------------------------
// cvt pre-passes: fp32 -> fp16
// ---------------------------------------------------------------------------
__global__ void cvt_roll_h_kernel(const float* __restrict__ x, __half* __restrict__ xh)
{
    size_t i4 = (size_t)blockIdx.x * 256 + threadIdx.x;
    size_t fi = i4 * 4;
    int m = (int)(fi >> 8);
    int c = (int)(fi & 255);
    int bi = m >> 14, t = m & 16383;
    int s = (t + SHIFT) & 16383;
    float4 v = *(const float4*)(x + (size_t)((bi << 14) + s) * CDIM + c);
    *(uint2*)(xh + fi) = make_uint2(h2u(__floats2half2_rn(v.x, v.y)),
                                    h2u(__floats2half2_rn(v.z, v.w)));
}

__global__ void cvt_h_kernel(const float* __restrict__ src, __half* __restrict__ dst, int n4)
{
    int i = blockIdx.x * 256 + threadIdx.x;
    if (i < n4) {
        float4 v = *(const float4*)(src + (size_t)i * 4);
        *(uint2*)(dst + (size_t)i * 4) = make_uint2(h2u(__floats2half2_rn(v.x, v.y)),
                                                    h2u(__floats2half2_rn(v.z, v.w)));
    }
}

// ---------------------------------------------------------------------------
// FP16 tensor-core attention (unchanged from R7 — passing).
// ---------------------------------------------------------------------------
__global__ void __launch_bounds__(128)
attn_f16_kernel(const __half* __restrict__ qkv,
                const float* __restrict__ rel_pos,
                __half* __restrict__ att)
{
    __shared__ __half Qs[64][40];
    __shared__ __half Ks[64][40];
    __shared__ __half VT[32][72];
    __shared__ __half Ps[64][72];
    __shared__ float  Os[64][36];
    __shared__ float  rels[128];
    __shared__ float  sinv[64];

    const int wi = blockIdx.x;
    const int h  = blockIdx.y;
    const int tid  = threadIdx.x;
    const int w    = tid >> 5;
    const int lane = tid & 31;
    const int g    = lane >> 2;
    const int tg   = lane & 3;
    const int mbase = wi * PWIN;
    const bool lastw = ((wi & (WPB - 1)) == (WPB - 1));

#pragma unroll
    for (int it = 0; it < 2; it++) {
        int idx = tid + it * 128;
        int j = idx >> 2, c8 = (idx & 3) * 8;
        const __half* base = qkv + (size_t)(mbase + j) * QKV_N + h * HDIM + c8;
        uint4 q4 = *(const uint4*)(base);
        uint4 k4 = *(const uint4*)(base + 256);
        uint4 v4 = *(const uint4*)(base + 512);
        *(uint4*)&Qs[j][c8] = q4;
        *(uint4*)&Ks[j][c8] = k4;
        __half vh[8];
        *(uint4*)vh = v4;
#pragma unroll
        for (int d = 0; d < 8; d++) VT[c8 + d][j] = vh[d];
    }
    if (tid < 127) rels[tid] = rel_pos[h * 127 + tid];
    __syncthreads();

    uint32_t qfr[2][4];
    {
        uint32_t qa = smem_u32(&Qs[w * 16 + (lane & 15)][(lane >> 4) * 8]);
        ldsm_x4(qfr[0], qa);
        ldsm_x4(qfr[1], qa + 32);
    }

    float sfr[8][4];
#pragma unroll
    for (int nt = 0; nt < 8; nt++)
#pragma unroll
        for (int r = 0; r < 4; r++) sfr[nt][r] = 0.0f;
    {
        uint32_t kb = smem_u32(&Ks[((lane >> 4) << 3) + (lane & 7)][((lane >> 3) & 1) * 8]);
#pragma unroll
        for (int ks = 0; ks < 2; ks++) {
#pragma unroll
            for (int ntp = 0; ntp < 4; ntp++) {
                uint32_t bb[4];
                ldsm_x4(bb, kb + (uint32_t)(ntp * 16 * 80) + ks * 32);
                uint32_t b0[2] = { bb[0], bb[1] };
                uint32_t b1[2] = { bb[2], bb[3] };
                mma_f16(sfr[ntp * 2],     qfr[ks], b0);
                mma_f16(sfr[ntp * 2 + 1], qfr[ks], b1);
            }
        }
    }

    const float scale = 0.17677669529663687f;
    const int i0 = w * 16 + g;
    const int i1 = i0 + 8;
    const int myside = w >> 1;
    float sum0 = 0.0f, sum1 = 0.0f;
#pragma unroll
    for (int nt = 0; nt < 8; nt++) {
        int j0 = nt * 8 + 2 * tg;
        float e00, e01, e10, e11;
        if (lastw && ((nt >> 2) != myside)) {
            e00 = e01 = e10 = e11 = 0.0f;
        } else {
            e00 = __expf(sfr[nt][0] * scale + rels[i0 - j0 + 63]);
            e01 = __expf(sfr[nt][1] * scale + rels[i0 - j0 + 62]);
            e10 = __expf(sfr[nt][2] * scale + rels[i1 - j0 + 63]);
            e11 = __expf(sfr[nt][3] * scale + rels[i1 - j0 + 62]);
        }
        sum0 += e00 + e01;
        sum1 += e10 + e11;
        *(uint32_t*)&Ps[i0][j0] = h2u(__floats2half2_rn(e00, e01));
        *(uint32_t*)&Ps[i1][j0] = h2u(__floats2half2_rn(e10, e11));
    }
    sum0 += __shfl_xor_sync(0xffffffffu, sum0, 1);
    sum0 += __shfl_xor_sync(0xffffffffu, sum0, 2);
    sum1 += __shfl_xor_sync(0xffffffffu, sum1, 1);
    sum1 += __shfl_xor_sync(0xffffffffu, sum1, 2);
    if (tg == 0) { sinv[i0] = 1.0f / sum0; sinv[i1] = 1.0f / sum1; }
    __syncwarp();

    float ofr[2][2][4];
#pragma unroll
    for (int mt = 0; mt < 2; mt++)
#pragma unroll
        for (int nt = 0; nt < 2; nt++)
#pragma unroll
            for (int r = 0; r < 4; r++) ofr[mt][nt][r] = 0.0f;
    {
        uint32_t va0 = smem_u32(&VT[(lane & 15)][(lane >> 4) * 8]);
        uint32_t va1 = smem_u32(&VT[16 + (lane & 15)][(lane >> 4) * 8]);
        uint32_t pb  = smem_u32(&Ps[w * 16 + ((lane >> 4) << 3) + (lane & 7)]
                                   [((lane >> 3) & 1) * 8]);
#pragma unroll
        for (int ks = 0; ks < 4; ks++) {
            uint32_t a0[4], a1[4], bb[4];
            ldsm_x4(a0, va0 + ks * 32);
            ldsm_x4(a1, va1 + ks * 32);
            ldsm_x4(bb, pb + ks * 32);
            uint32_t b0[2] = { bb[0], bb[1] };
            uint32_t b1[2] = { bb[2], bb[3] };
            mma_f16(ofr[0][0], a0, b0);
            mma_f16(ofr[0][1], a0, b1);
            mma_f16(ofr[1][0], a1, b0);
            mma_f16(ofr[1][1], a1, b1);
        }
    }

#pragma unroll
    for (int mt = 0; mt < 2; mt++)
#pragma unroll
        for (int nt = 0; nt < 2; nt++) {
            int d = mt * 16 + g;
            int i = w * 16 + nt * 8 + 2 * tg;
            Os[i][d]         = ofr[mt][nt][0];
            Os[i + 1][d]     = ofr[mt][nt][1];
            Os[i][d + 8]     = ofr[mt][nt][2];
            Os[i + 1][d + 8] = ofr[mt][nt][3];
        }
    __syncthreads();

#pragma unroll
    for (int it = 0; it < 2; it++) {
        int idx = tid + it * 128;
        int i = idx >> 2, d8 = (idx & 3) * 8;
        float inv = sinv[i];
        float4 v0 = *(float4*)&Os[i][d8];
        float4 v1 = *(float4*)&Os[i][d8 + 4];
        uint4 o;
        o.x = h2u(__floats2half2_rn(v0.x * inv, v0.y * inv));
        o.y = h2u(__floats2half2_rn(v0.z * inv, v0.w * inv));
        o.z = h2u(__floats2half2_rn(v1.x * inv, v1.y * inv));
        o.w = h2u(__floats2half2_rn(v1.z * inv, v1.w * inv));
        *(uint4*)(att + (size_t)(mbase + i) * CDIM + h * HDIM + d8) = o;
    }
}

// ---------------------------------------------------------------------------
extern "C" void kernel_launch(void* const* d_in, const int* in_sizes, int n_in,
                              void* d_out, int out_size)
{
    const float* x       = (const float*)d_in[0];
    const float* w_qkv   = (const float*)d_in[1];
    const float* b_qkv   = (const float*)d_in[2];
    const float* rel_pos = (const float*)d_in[3];
    const float* w_out   = (const float*)d_in[4];
    const float* b_out   = (const float*)d_in[5];
    float* out = (float*)d_out;

    __half *qkvp, *attp, *xhp, *wqkvp, *woutp;
    cudaGetSymbolAddress((void**)&qkvp,  g_qkv);
    cudaGetSymbolAddress((void**)&attp,  g_att);
    cudaGetSymbolAddress((void**)&xhp,   g_xh);
    cudaGetSymbolAddress((void**)&wqkvp, g_wqkvh);
    cudaGetSymbolAddress((void**)&woutp, g_wouth);

    // K0: fp16 pre-conversion (roll folded into x copy)
    cvt_roll_h_kernel<<<(MTOT * CDIM / 4) / 256, 256>>>(x, xhp);
    cvt_h_kernel<<<(QKV_N * CDIM / 4 + 255) / 256, 256>>>(w_qkv, wqkvp, QKV_N * CDIM / 4);
    cvt_h_kernel<<<(CDIM * CDIM / 4 + 255) / 256, 256>>>(w_out, woutp, CDIM * CDIM / 4);

    // K1: QKV projection (fp16 out)
    {
        dim3 grid(QKV_N / 128, MTOT / 128);   // (6, 1024)
        gemm_f16_kernel<false, __half><<<grid, 128>>>(xhp, wqkvp, b_qkv, qkvp, QKV_N);
    }
    // K2: windowed attention (fp16 tensor cores)
    {
        dim3 grid(NWIN, NHEADS);
        attn_f16_kernel<<<grid, 128>>>(qkvp, rel_pos, attp);
    }
    // K3: output projection (fp32 out, roll on write)
    {
        dim3 grid(CDIM / 128, MTOT / 128);    // (2, 1024)
        gemm_f16_kernel<true, float><<<grid, 128>>>(attp, woutp, b_out, out, CDIM);
    }
}

// round 11
// speedup vs baseline: 1.0895x; 1.0895x over previous
#include <cuda_runtime.h>
#include <cuda_fp16.h>
#include <cstdint>

// ---------------------------------------------------------------------------
// Shifted-window MSA. B=8, NSEQ=16384, C=256, P=64, SHIFT=32, NH=8, HD=32.
//   K0: cvt x(rolled)->fp16, w_qkv->fp16, w_out->fp16
//   K1: QKV GEMM (fp16 mma, 64x32 warp tile, cp.async 2-stage) -> g_qkv (fp16)
//   K2: attention (fp16 mma, per window-head)                  -> g_att (fp16)
//   K3: out GEMM (same GEMM, roll on write)                    -> d_out (fp32)
// tcgen05 unusable: harness ptxas targets sm_103 (no 'a' features).
// ---------------------------------------------------------------------------

#define BATCH   8
#define NSEQ    16384
#define CDIM    256
#define PWIN    64
#define SHIFT   32
#define NHEADS  8
#define HDIM    32
#define MTOT    (BATCH * NSEQ)
#define QKV_N   768
#define NWIN    (MTOT / PWIN)
#define WPB     (NSEQ / PWIN)

__device__ __half g_qkv [(size_t)MTOT * QKV_N];
__device__ __half g_att [(size_t)MTOT * CDIM];
__device__ __half g_xh  [(size_t)MTOT * CDIM];
__device__ __half g_wqkvh[(size_t)QKV_N * CDIM];
__device__ __half g_wouth[(size_t)CDIM * CDIM];

// ---------------------------------------------------------------------------
__device__ __forceinline__ uint32_t smem_u32(const void* p) {
    return (uint32_t)__cvta_generic_to_shared(p);
}
__device__ __forceinline__ void mma_f16(float (&d)[4],
                                        const uint32_t (&a)[4],
                                        const uint32_t (&b)[2]) {
    asm volatile(
        "mma.sync.aligned.m16n8k16.row.col.f32.f16.f16.f32 "
        "{%0,%1,%2,%3}, {%4,%5,%6,%7}, {%8,%9}, {%0,%1,%2,%3};"
        : "+f"(d[0]), "+f"(d[1]), "+f"(d[2]), "+f"(d[3])
        : "r"(a[0]), "r"(a[1]), "r"(a[2]), "r"(a[3]), "r"(b[0]), "r"(b[1]));
}
__device__ __forceinline__ void ldsm_x4(uint32_t (&r)[4], uint32_t addr) {
    asm volatile("ldmatrix.sync.aligned.m8n8.x4.shared.b16 {%0,%1,%2,%3}, [%4];"
        : "=r"(r[0]), "=r"(r[1]), "=r"(r[2]), "=r"(r[3]) : "r"(addr));
}
__device__ __forceinline__ uint32_t h2u(__half2 h) {
    return *reinterpret_cast<uint32_t*>(&h);
}
__device__ __forceinline__ void cp_async16(uint32_t dst, const void* src) {
    asm volatile("cp.async.cg.shared.global [%0], [%1], 16;"
                 :: "r"(dst), "l"(src));
}
#define CP_COMMIT() asm volatile("cp.async.commit_group;" ::: "memory")
#define CP_WAIT(n)  asm volatile("cp.async.wait_group %0;" :: "n"(n) : "memory")

// ---------------------------------------------------------------------------
// FP16 GEMM: C[m,n] = sum_k A[m,k]*W[n,k] + bias[n]
// BM=BN=128, BK=64, 256 threads = 8 warps, warp tile 64x32, ldmatrix frags.
// 2-stage cp.async double buffering: gmem->smem direct, overlapped with MMA.
// Row stride 72 halves (144B): LDSM phase conflict-free, 16B aligned chunks.
// Smem: 2 stages x (A 18KB + B 18KB) = 72KB dynamic.
// ---------------------------------------------------------------------------
#define HBK 64
#define NKT (CDIM / HBK)            // 4
#define ROWB 144                    // row stride bytes
#define STG_B (2 * 128 * ROWB)      // stage stride = 36864 B
#define BOFF (128 * ROWB)           // B matrix offset within stage = 18432 B
#define GSMEM (2 * STG_B)           // 73728 B

template<bool ROLL_OUT, typename OutT>
__global__ void __launch_bounds__(256, 2)
gemm_f16_kernel(const __half* __restrict__ A,
                const __half* __restrict__ W,
                const float* __restrict__ bias,
                OutT* __restrict__ Cout,
                int Ncols)
{
    extern __shared__ __half smem[];
    const uint32_t sbase = smem_u32(smem);

    const int bm = blockIdx.y * 128;
    const int bn = blockIdx.x * 128;

    const int t    = threadIdx.x;
    const int warp = t >> 5;
    const int lane = t & 31;
    const int g    = lane >> 2;
    const int tg   = lane & 3;

    const int wm = (warp & 1) * 64;
    const int wn = (warp >> 1) * 32;

    // gmem->smem map: 128 rows x 8 chunks(16B) per matrix, 4 chunks/thread
    int arow[4], ac[4];
#pragma unroll
    for (int i = 0; i < 4; i++) {
        int id = t + i * 256;
        arow[i] = id >> 3;
        ac[i]   = id & 7;
    }
    const __half* Ab = A + (size_t)bm * CDIM;
    const __half* Wb = W + (size_t)bn * CDIM;

    // per-thread cp.async smem destinations (stage 0)
    uint32_t dstA[4];
#pragma unroll
    for (int i = 0; i < 4; i++)
        dstA[i] = sbase + (uint32_t)(arow[i] * ROWB + ac[i] * 16);

    // ldmatrix base addresses (stage 0)
    uint32_t aAddr[4], bAddr[2];
#pragma unroll
    for (int mt = 0; mt < 4; mt++)
        aAddr[mt] = sbase + (uint32_t)((wm + mt * 16 + (lane & 15)) * ROWB
                                       + (lane >> 4) * 16);
#pragma unroll
    for (int ntp = 0; ntp < 2; ntp++)
        bAddr[ntp] = sbase + BOFF
                   + (uint32_t)((wn + ntp * 16 + ((lane >> 4) << 3) + (lane & 7)) * ROWB
                                + ((lane >> 3) & 1) * 16);

    float acc[4][4][4];
#pragma unroll
    for (int mt = 0; mt < 4; mt++)
#pragma unroll
        for (int nt = 0; nt < 4; nt++)
#pragma unroll
            for (int r = 0; r < 4; r++) acc[mt][nt][r] = 0.0f;

    // ---- prologue: issue stages 0 and 1 ----
#pragma unroll
    for (int i = 0; i < 4; i++) {
        cp_async16(dstA[i],        Ab + (size_t)arow[i] * CDIM + ac[i] * 8);
        cp_async16(dstA[i] + BOFF, Wb + (size_t)arow[i] * CDIM + ac[i] * 8);
    }
    CP_COMMIT();
#pragma unroll
    for (int i = 0; i < 4; i++) {
        cp_async16(dstA[i] + STG_B,        Ab + (size_t)arow[i] * CDIM + HBK + ac[i] * 8);
        cp_async16(dstA[i] + STG_B + BOFF, Wb + (size_t)arow[i] * CDIM + HBK + ac[i] * 8);
    }
    CP_COMMIT();

#pragma unroll 1
    for (int kt = 0; kt < NKT; kt++) {
        if (kt < NKT - 1) CP_WAIT(1);
        else              CP_WAIT(0);
        __syncthreads();                       // stage (kt&1) data visible

        const uint32_t so = (kt & 1) ? (uint32_t)STG_B : 0u;
#pragma unroll
        for (int ks = 0; ks < 4; ks++) {
            const uint32_t koff = ks * 32;     // 16 halves
            uint32_t afr[4][4], bp[2][4];
#pragma unroll
            for (int mt = 0; mt < 4; mt++) ldsm_x4(afr[mt], aAddr[mt] + so + koff);
#pragma unroll
            for (int ntp = 0; ntp < 2; ntp++) ldsm_x4(bp[ntp], bAddr[ntp] + so + koff);
#pragma unroll
            for (int mt = 0; mt < 4; mt++)
#pragma unroll
                for (int nt = 0; nt < 4; nt++) {
                    uint32_t bfr[2] = { bp[nt >> 1][(nt & 1) * 2],
                                        bp[nt >> 1][(nt & 1) * 2 + 1] };
                    mma_f16(acc[mt][nt], afr[mt], bfr);
                }
        }

        if (kt + 2 < NKT) {
            __syncthreads();                   // all warps done reading this stage
            const int k0 = (kt + 2) * HBK;
#pragma unroll
            for (int i = 0; i < 4; i++) {
                cp_async16(dstA[i] + so,        Ab + (size_t)arow[i] * CDIM + k0 + ac[i] * 8);
                cp_async16(dstA[i] + so + BOFF, Wb + (size_t)arow[i] * CDIM + k0 + ac[i] * 8);
            }
            CP_COMMIT();
        }
    }

    // ---- epilogue: bias + optional output roll ----
#pragma unroll
    for (int mt = 0; mt < 4; mt++) {
        int m0 = bm + wm + mt * 16 + g;
        int m1 = m0 + 8;
        int bi0 = m0 >> 14, t0 = m0 & 16383;
        int bi1 = m1 >> 14, t1 = m1 & 16383;
        int d0 = ROLL_OUT ? ((t0 + SHIFT) & 16383) : t0;
        int d1 = ROLL_OUT ? ((t1 + SHIFT) & 16383) : t1;
        OutT* row0 = Cout + (size_t)((bi0 << 14) + d0) * Ncols;
        OutT* row1 = Cout + (size_t)((bi1 << 14) + d1) * Ncols;
#pragma unroll
        for (int nt = 0; nt < 4; nt++) {
            int col = bn + wn + nt * 8 + 2 * tg;
            float b0 = bias[col], b1 = bias[col + 1];
            if constexpr (sizeof(OutT) == 4) {
                *(float2*)((float*)row0 + col) =
                    make_float2(acc[mt][nt][0] + b0, acc[mt][nt][1] + b1);
                *(float2*)((float*)row1 + col) =
                    make_float2(acc[mt][nt][2] + b0, acc[mt][nt][3] + b1);
            } else {
                *(uint32_t*)((__half*)row0 + col) =
                    h2u(__floats2half2_rn(acc[mt][nt][0] + b0, acc[mt][nt][1] + b1));
                *(uint32_t*)((__half*)row1 + col) =
                    h2u(__floats2half2_rn(acc[mt][nt][2] + b0, acc[mt][nt][3] + b1));
            }
        }
    }
}

// ---------------------------------------------------------------------------
// cvt pre-passes: fp32 -> fp16
// ---------------------------------------------------------------------------
__global__ void cvt_roll_h_kernel(const float* __restrict__ x, __half* __restrict__ xh)
{
    size_t i4 = (size_t)blockIdx.x * 256 + threadIdx.x;
    size_t fi = i4 * 4;
    int m = (int)(fi >> 8);
    int c = (int)(fi & 255);
    int bi = m >> 14, t = m & 16383;
    int s = (t + SHIFT) & 16383;
    float4 v = *(const float4*)(x + (size_t)((bi << 14) + s) * CDIM + c);
    *(uint2*)(xh + fi) = make_uint2(h2u(__floats2half2_rn(v.x, v.y)),
                                    h2u(__floats2half2_rn(v.z, v.w)));
}

__global__ void cvt_h_kernel(const float* __restrict__ src, __half* __restrict__ dst, int n4)
{
    int i = blockIdx.x * 256 + threadIdx.x;
    if (i < n4) {
        float4 v = *(const float4*)(src + (size_t)i * 4);
        *(uint2*)(dst + (size_t)i * 4) = make_uint2(h2u(__floats2half2_rn(v.x, v.y)),
                                                    h2u(__floats2half2_rn(v.z, v.w)));
    }
}

// ---------------------------------------------------------------------------
// FP16 tensor-core attention (unchanged from R7 — passing).
// ---------------------------------------------------------------------------
__global__ void __launch_bounds__(128)
attn_f16_kernel(const __half* __restrict__ qkv,
                const float* __restrict__ rel_pos,
                __half* __restrict__ att)
{
    __shared__ __half Qs[64][40];
    __shared__ __half Ks[64][40];
    __shared__ __half VT[32][72];
    __shared__ __half Ps[64][72];
    __shared__ float  Os[64][36];
    __shared__ float  rels[128];
    __shared__ float  sinv[64];

    const int wi = blockIdx.x;
    const int h  = blockIdx.y;
    const int tid  = threadIdx.x;
    const int w    = tid >> 5;
    const int lane = tid & 31;
    const int g    = lane >> 2;
    const int tg   = lane & 3;
    const int mbase = wi * PWIN;
    const bool lastw = ((wi & (WPB - 1)) == (WPB - 1));

#pragma unroll
    for (int it = 0; it < 2; it++) {
        int idx = tid + it * 128;
        int j = idx >> 2, c8 = (idx & 3) * 8;
        const __half* base = qkv + (size_t)(mbase + j) * QKV_N + h * HDIM + c8;
        uint4 q4 = *(const uint4*)(base);
        uint4 k4 = *(const uint4*)(base + 256);
        uint4 v4 = *(const uint4*)(base + 512);
        *(uint4*)&Qs[j][c8] = q4;
        *(uint4*)&Ks[j][c8] = k4;
        __half vh[8];
        *(uint4*)vh = v4;
#pragma unroll
        for (int d = 0; d < 8; d++) VT[c8 + d][j] = vh[d];
    }
    if (tid < 127) rels[tid] = rel_pos[h * 127 + tid];
    __syncthreads();

    uint32_t qfr[2][4];
    {
        uint32_t qa = smem_u32(&Qs[w * 16 + (lane & 15)][(lane >> 4) * 8]);
        ldsm_x4(qfr[0], qa);
        ldsm_x4(qfr[1], qa + 32);
    }

    float sfr[8][4];
#pragma unroll
    for (int nt = 0; nt < 8; nt++)
#pragma unroll
        for (int r = 0; r < 4; r++) sfr[nt][r] = 0.0f;
    {
        uint32_t kb = smem_u32(&Ks[((lane >> 4) << 3) + (lane & 7)][((lane >> 3) & 1) * 8]);
#pragma unroll
        for (int ks = 0; ks < 2; ks++) {
#pragma unroll
            for (int ntp = 0; ntp < 4; ntp++) {
                uint32_t bb[4];
                ldsm_x4(bb, kb + (uint32_t)(ntp * 16 * 80) + ks * 32);
                uint32_t b0[2] = { bb[0], bb[1] };
                uint32_t b1[2] = { bb[2], bb[3] };
                mma_f16(sfr[ntp * 2],     qfr[ks], b0);
                mma_f16(sfr[ntp * 2 + 1], qfr[ks], b1);
            }
        }
    }

    const float scale = 0.17677669529663687f;
    const int i0 = w * 16 + g;
    const int i1 = i0 + 8;
    const int myside = w >> 1;
    float sum0 = 0.0f, sum1 = 0.0f;
#pragma unroll
    for (int nt = 0; nt < 8; nt++) {
        int j0 = nt * 8 + 2 * tg;
        float e00, e01, e10, e11;
        if (lastw && ((nt >> 2) != myside)) {
            e00 = e01 = e10 = e11 = 0.0f;
        } else {
            e00 = __expf(sfr[nt][0] * scale + rels[i0 - j0 + 63]);
            e01 = __expf(sfr[nt][1] * scale + rels[i0 - j0 + 62]);
            e10 = __expf(sfr[nt][2] * scale + rels[i1 - j0 + 63]);
            e11 = __expf(sfr[nt][3] * scale + rels[i1 - j0 + 62]);
        }
        sum0 += e00 + e01;
        sum1 += e10 + e11;
        *(uint32_t*)&Ps[i0][j0] = h2u(__floats2half2_rn(e00, e01));
        *(uint32_t*)&Ps[i1][j0] = h2u(__floats2half2_rn(e10, e11));
    }
    sum0 += __shfl_xor_sync(0xffffffffu, sum0, 1);
    sum0 += __shfl_xor_sync(0xffffffffu, sum0, 2);
    sum1 += __shfl_xor_sync(0xffffffffu, sum1, 1);
    sum1 += __shfl_xor_sync(0xffffffffu, sum1, 2);
    if (tg == 0) { sinv[i0] = 1.0f / sum0; sinv[i1] = 1.0f / sum1; }
    __syncwarp();

    float ofr[2][2][4];
#pragma unroll
    for (int mt = 0; mt < 2; mt++)
#pragma unroll
        for (int nt = 0; nt < 2; nt++)
#pragma unroll
            for (int r = 0; r < 4; r++) ofr[mt][nt][r] = 0.0f;
    {
        uint32_t va0 = smem_u32(&VT[(lane & 15)][(lane >> 4) * 8]);
        uint32_t va1 = smem_u32(&VT[16 + (lane & 15)][(lane >> 4) * 8]);
        uint32_t pb  = smem_u32(&Ps[w * 16 + ((lane >> 4) << 3) + (lane & 7)]
                                   [((lane >> 3) & 1) * 8]);
#pragma unroll
        for (int ks = 0; ks < 4; ks++) {
            uint32_t a0[4], a1[4], bb[4];
            ldsm_x4(a0, va0 + ks * 32);
            ldsm_x4(a1, va1 + ks * 32);
            ldsm_x4(bb, pb + ks * 32);
            uint32_t b0[2] = { bb[0], bb[1] };
            uint32_t b1[2] = { bb[2], bb[3] };
            mma_f16(ofr[0][0], a0, b0);
            mma_f16(ofr[0][1], a0, b1);
            mma_f16(ofr[1][0], a1, b0);
            mma_f16(ofr[1][1], a1, b1);
        }
    }

#pragma unroll
    for (int mt = 0; mt < 2; mt++)
#pragma unroll
        for (int nt = 0; nt < 2; nt++) {
            int d = mt * 16 + g;
            int i = w * 16 + nt * 8 + 2 * tg;
            Os[i][d]         = ofr[mt][nt][0];
            Os[i + 1][d]     = ofr[mt][nt][1];
            Os[i][d + 8]     = ofr[mt][nt][2];
            Os[i + 1][d + 8] = ofr[mt][nt][3];
        }
    __syncthreads();

#pragma unroll
    for (int it = 0; it < 2; it++) {
        int idx = tid + it * 128;
        int i = idx >> 2, d8 = (idx & 3) * 8;
        float inv = sinv[i];
        float4 v0 = *(float4*)&Os[i][d8];
        float4 v1 = *(float4*)&Os[i][d8 + 4];
        uint4 o;
        o.x = h2u(__floats2half2_rn(v0.x * inv, v0.y * inv));
        o.y = h2u(__floats2half2_rn(v0.z * inv, v0.w * inv));
        o.z = h2u(__floats2half2_rn(v1.x * inv, v1.y * inv));
        o.w = h2u(__floats2half2_rn(v1.z * inv, v1.w * inv));
        *(uint4*)(att + (size_t)(mbase + i) * CDIM + h * HDIM + d8) = o;
    }
}

// ---------------------------------------------------------------------------
extern "C" void kernel_launch(void* const* d_in, const int* in_sizes, int n_in,
                              void* d_out, int out_size)
{
    const float* x       = (const float*)d_in[0];
    const float* w_qkv   = (const float*)d_in[1];
    const float* b_qkv   = (const float*)d_in[2];
    const float* rel_pos = (const float*)d_in[3];
    const float* w_out   = (const float*)d_in[4];
    const float* b_out   = (const float*)d_in[5];
    float* out = (float*)d_out;

    __half *qkvp, *attp, *xhp, *wqkvp, *woutp;
    cudaGetSymbolAddress((void**)&qkvp,  g_qkv);
    cudaGetSymbolAddress((void**)&attp,  g_att);
    cudaGetSymbolAddress((void**)&xhp,   g_xh);
    cudaGetSymbolAddress((void**)&wqkvp, g_wqkvh);
    cudaGetSymbolAddress((void**)&woutp, g_wouth);

    cudaFuncSetAttribute(gemm_f16_kernel<false, __half>,
                         cudaFuncAttributeMaxDynamicSharedMemorySize, GSMEM);
    cudaFuncSetAttribute(gemm_f16_kernel<true, float>,
                         cudaFuncAttributeMaxDynamicSharedMemorySize, GSMEM);

    // K0: fp16 pre-conversion (roll folded into x copy)
    cvt_roll_h_kernel<<<(MTOT * CDIM / 4) / 256, 256>>>(x, xhp);
    cvt_h_kernel<<<(QKV_N * CDIM / 4 + 255) / 256, 256>>>(w_qkv, wqkvp, QKV_N * CDIM / 4);
    cvt_h_kernel<<<(CDIM * CDIM / 4 + 255) / 256, 256>>>(w_out, woutp, CDIM * CDIM / 4);

    // K1: QKV projection (fp16 out)
    {
        dim3 grid(QKV_N / 128, MTOT / 128);   // (6, 1024)
        gemm_f16_kernel<false, __half><<<grid, 256, GSMEM>>>(xhp, wqkvp, b_qkv, qkvp, QKV_N);
    }
    // K2: windowed attention (fp16 tensor cores)
    {
        dim3 grid(NWIN, NHEADS);
        attn_f16_kernel<<<grid, 128>>>(qkvp, rel_pos, attp);
    }
    // K3: output projection (fp32 out, roll on write)
    {
        dim3 grid(CDIM / 128, MTOT / 128);    // (2, 1024)
        gemm_f16_kernel<true, float><<<grid, 256, GSMEM>>>(attp, woutp, b_out, out, CDIM);
    }
}